// round 13
// baseline (speedup 1.0000x reference)
#include <cuda_runtime.h>
#include <cuda_bf16.h>
#include <cstdint>
#include <math.h>

// Problem constants
#define NN 4096
#define HH 128
#define EE 131072
#define SZ (NN * HH)

// ---------------- scratch (static device arrays; no allocation) ----------------
__device__ float g_h1[SZ];
__device__ float g_h2[SZ];
__device__ float g_z1[SZ];
__device__ float g_z3[SZ];
__device__ float g_qkv[2 * NN * 3 * HH];
__device__ float g_obar[SZ];
__device__ float g_h1mix[SZ];
__device__ float g_part[16 * SZ];         // split-K partials (2 batches x KS=8)
__device__ float g_Yt[2 * HH * NN];       // transposed tf32 Y buffers
__device__ float g_h1t[HH * NN];          // h1^T tf32
__device__ float g_mix[2 * SZ];
__device__ float g_fus[2 * SZ];
__device__ float g_rs1[8 * NN];           // rowsum(G1) partials (KS=8)
__device__ float g_rs3[8 * NN];           // rowsum(G3) partials (KS=8)

// ---------------- helpers -------------------------------------------------------
__device__ __forceinline__ unsigned tf32r(float v) {
    unsigned u;
    asm("cvt.rna.tf32.f32 %0, %1;" : "=r"(u) : "f"(v));
    return u;
}

#define MMA_TF32(d, a0, a1, a2, a3, b0, b1)                                   \
    asm volatile(                                                             \
        "mma.sync.aligned.m16n8k8.row.col.f32.tf32.tf32.f32 "                 \
        "{%0,%1,%2,%3}, {%4,%5,%6,%7}, {%8,%9}, {%0,%1,%2,%3};"               \
        : "+f"(d[0]), "+f"(d[1]), "+f"(d[2]), "+f"(d[3])                      \
        : "r"(a0), "r"(a1), "r"(a2), "r"(a3), "r"(b0), "r"(b1))

// =======================================================================
// tf32 GEMM core, 64x128 CTA tile: C[M,Nc] = A[M,K] @ B[K,Nc],
// B transposed [Nc][K]. grid.x covers M/64. KS>1: partial at C + kz*M*Nc.
// Optional rowsum(A) partial rs[kz*M + row].
// Warp grid 2x4, warp tile 32x32, acc 32 regs/thread.
// =======================================================================
__device__ __forceinline__ void tgemm_core(
    const float* __restrict__ A, const float* __restrict__ Bt,
    float* __restrict__ C, int M, int K, int Nc, int col0,
    const float* __restrict__ bias, int KS, int kz, float* __restrict__ rs)
{
    __shared__ float sA[64][36];
    __shared__ float sB[128][36];

    const int tid  = threadIdx.x;
    const int row0 = blockIdx.x * 64;
    const int kiters = K / (32 * KS);
    const int kbase  = kz * kiters * 32;

    const int warp = tid >> 5, lane = tid & 31;
    const int wm = warp >> 2, wn = warp & 3;          // 2 x 4 warp grid
    const int grp = lane >> 2, thr4 = lane & 3;

    float acc[2][4][4];
#pragma unroll
    for (int mf = 0; mf < 2; mf++)
#pragma unroll
        for (int nf = 0; nf < 4; nf++)
#pragma unroll
            for (int i = 0; i < 4; i++) acc[mf][nf][i] = 0.0f;

    // A loader: 64 rows x 32 cols, 4 threads/row, 8 floats each
    const int l_ra = tid >> 2;
    const int l_ca = (tid & 3) * 8;
    // B loader: 128 rows x 32 cols, 2 threads/row, 16 floats each
    const int l_rb = tid >> 1;
    const int l_cb = (tid & 1) * 16;
    const float* gA = A  + (size_t)(row0 + l_ra) * K + kbase + l_ca;
    const float* gB = Bt + (size_t)(col0 + l_rb) * K + kbase + l_cb;

    float4 pa[2], pb[4];
#pragma unroll
    for (int i = 0; i < 2; i++) pa[i] = *(const float4*)(gA + i * 4);
#pragma unroll
    for (int i = 0; i < 4; i++) pb[i] = *(const float4*)(gB + i * 4);

    float asum = 0.0f;

    for (int it = 0; it < kiters; it++) {
#pragma unroll
        for (int i = 0; i < 2; i++) {
            uint4 t;
            t.x = tf32r(pa[i].x); t.y = tf32r(pa[i].y);
            t.z = tf32r(pa[i].z); t.w = tf32r(pa[i].w);
            *(uint4*)&sA[l_ra][l_ca + i * 4] = t;
        }
#pragma unroll
        for (int i = 0; i < 4; i++) {
            uint4 t;
            t.x = tf32r(pb[i].x); t.y = tf32r(pb[i].y);
            t.z = tf32r(pb[i].z); t.w = tf32r(pb[i].w);
            *(uint4*)&sB[l_rb][l_cb + i * 4] = t;
        }
        if (rs) {
#pragma unroll
            for (int i = 0; i < 2; i++)
                asum += (pa[i].x + pa[i].y) + (pa[i].z + pa[i].w);
        }
        __syncthreads();

        if (it + 1 < kiters) {
            const int ko = (it + 1) * 32;
#pragma unroll
            for (int i = 0; i < 2; i++) pa[i] = *(const float4*)(gA + ko + i * 4);
#pragma unroll
            for (int i = 0; i < 4; i++) pb[i] = *(const float4*)(gB + ko + i * 4);
        }

#pragma unroll
        for (int koff = 0; koff < 32; koff += 8) {
            const int c0 = koff + thr4;
            unsigned a[2][4];
#pragma unroll
            for (int mf = 0; mf < 2; mf++) {
                const int mb = wm * 32 + mf * 16;
                a[mf][0] = *(const unsigned*)&sA[mb + grp][c0];
                a[mf][1] = *(const unsigned*)&sA[mb + grp + 8][c0];
                a[mf][2] = *(const unsigned*)&sA[mb + grp][c0 + 4];
                a[mf][3] = *(const unsigned*)&sA[mb + grp + 8][c0 + 4];
            }
#pragma unroll
            for (int nf = 0; nf < 4; nf++) {
                const int nb = wn * 32 + nf * 8;
                unsigned b0 = *(const unsigned*)&sB[nb + grp][c0];
                unsigned b1 = *(const unsigned*)&sB[nb + grp][c0 + 4];
#pragma unroll
                for (int mf = 0; mf < 2; mf++)
                    MMA_TF32(acc[mf][nf], a[mf][0], a[mf][1], a[mf][2], a[mf][3], b0, b1);
            }
        }
        __syncthreads();
    }

    if (rs) {
        // reduce across the 4 loader-threads of each A row (consecutive tids)
        asum += __shfl_xor_sync(0xffffffffu, asum, 1);
        asum += __shfl_xor_sync(0xffffffffu, asum, 2);
        if ((tid & 3) == 0)
            rs[(size_t)kz * M + row0 + l_ra] = asum;
    }

    float* Co = (KS > 1) ? C + (size_t)kz * M * Nc : C;
#pragma unroll
    for (int mf = 0; mf < 2; mf++) {
        const int m = row0 + wm * 32 + mf * 16 + grp;
#pragma unroll
        for (int nf = 0; nf < 4; nf++) {
            const int n = col0 + wn * 32 + nf * 8 + thr4 * 2;
            float b0 = 0.f, b1 = 0.f;
            if (bias) { b0 = bias[n]; b1 = bias[n + 1]; }
            float2 v0 = make_float2(acc[mf][nf][0] + b0, acc[mf][nf][1] + b1);
            float2 v1 = make_float2(acc[mf][nf][2] + b0, acc[mf][nf][3] + b1);
            *(float2*)(Co + (size_t)m * Nc + n) = v0;
            *(float2*)(Co + (size_t)(m + 8) * Nc + n) = v1;
        }
    }
}

// standard entry: grid (M/64, Nc/128, KS)
__global__ __launch_bounds__(256, 3) void tgemm_kernel(
    const float* __restrict__ A, const float* __restrict__ Bt,
    float* __restrict__ C, int M, int K, int Nc, const float* __restrict__ bias,
    float* __restrict__ rs)
{
    tgemm_core(A, Bt, C, M, K, Nc, blockIdx.y * 128, bias,
               gridDim.z, blockIdx.z, blockIdx.y == 0 ? rs : nullptr);
}

// batched-by-2 entry (Nc=128): grid (M/64, 2, KS)
__global__ __launch_bounds__(256, 3) void tgemm2_kernel(
    const float* __restrict__ A0, const float* __restrict__ A1,
    const float* __restrict__ B0, const float* __restrict__ B1,
    float* __restrict__ C0, float* __restrict__ C1,
    float* __restrict__ rsa, float* __restrict__ rsb,
    int M, int K)
{
    const float* A = blockIdx.y ? A1 : A0;
    const float* B = blockIdx.y ? B1 : B0;
    float*       C = blockIdx.y ? C1 : C0;
    float*       r = blockIdx.y ? rsb : rsa;
    tgemm_core(A, B, C, M, K, 128, 0, nullptr, gridDim.z, blockIdx.z, r);
}

// ---------------- split-K reduce + epilogue (KS partials) ----------------------
__global__ void reduceN_kernel(const float* __restrict__ part, float* __restrict__ C,
                               const float* __restrict__ resid, int do_relu,
                               const float* __restrict__ scale_ptr, int KS)
{
    int i = (blockIdx.x * blockDim.x + threadIdx.x) * 4;
    if (i >= SZ) return;
    float v[4] = {0.f, 0.f, 0.f, 0.f};
    for (int z = 0; z < KS; z++) {
        float4 p = *(const float4*)(part + (size_t)z * SZ + i);
        v[0] += p.x; v[1] += p.y; v[2] += p.z; v[3] += p.w;
    }
    if (resid) {
        float4 r = *(const float4*)(resid + i);
        v[0] += r.x; v[1] += r.y; v[2] += r.z; v[3] += r.w;
    }
    float s = scale_ptr ? *scale_ptr : 1.0f;
#pragma unroll
    for (int j = 0; j < 4; j++) {
        if (do_relu) v[j] = fmaxf(v[j], 0.0f);
        v[j] *= s;
    }
    *(float4*)(C + i) = make_float4(v[0], v[1], v[2], v[3]);
}

// ---- reduce + relu + ALSO write tf32 transposed copy (for h1) ------------------
// grid (NN/32, HH/32), block (32, 8)
__global__ void reduceN_t_kernel(const float* __restrict__ part, int KS,
                                 float* __restrict__ O, float* __restrict__ Ot)
{
    __shared__ float t[32][33];
    const int r0 = blockIdx.x * 32, c0 = blockIdx.y * 32;
    const int tx = threadIdx.x, ty = threadIdx.y;
#pragma unroll
    for (int q = 0; q < 4; q++) {
        int r = r0 + ty + q * 8;
        int c = c0 + tx;
        float v = 0.f;
        for (int z = 0; z < KS; z++)
            v += part[(size_t)z * SZ + (size_t)r * HH + c];
        v = fmaxf(v, 0.0f);
        O[(size_t)r * HH + c] = v;
        t[ty + q * 8][tx] = v;
    }
    __syncthreads();
#pragma unroll
    for (int q = 0; q < 4; q++) {
        int c = c0 + ty + q * 8;
        int r = r0 + tx;
        Ot[(size_t)c * NN + r] = __uint_as_float(tf32r(t[tx][ty + q * 8]));
    }
}

// =======================================================================
// FFMA small GEMM (K=128, ncols=128): Yt[c][r] = tf32(A@B + b)
// =======================================================================
#define BM 16
#define BK 32

__device__ __forceinline__ void sgemm_t_core(
    const float* __restrict__ A, const float* __restrict__ B,
    float* __restrict__ Yt, int M, int K, int ncols,
    const float* __restrict__ bias)
{
    __shared__ float As[BK][BM];
    __shared__ float Bs[BK][128];

    const int tid = threadIdx.x;
    const int tx = tid & 31;
    const int ty = tid >> 5;
    const int row0 = blockIdx.x * BM;

    float acc[4][4];
#pragma unroll
    for (int i = 0; i < 4; i++)
#pragma unroll
        for (int j = 0; j < 4; j++) acc[i][j] = 0.0f;

    const int a_row = tid >> 3;
    const int a_k4  = (tid & 7) * 4;
    const int b_c4  = (tid & 31) * 4;
    const int b_kr  = tid >> 5;

    for (int kt = 0; kt < K; kt += BK) {
        float4 a = *(const float4*)(A + (size_t)(row0 + a_row) * K + kt + a_k4);
        As[a_k4 + 0][a_row] = a.x;
        As[a_k4 + 1][a_row] = a.y;
        As[a_k4 + 2][a_row] = a.z;
        As[a_k4 + 3][a_row] = a.w;
#pragma unroll
        for (int i = 0; i < 8; i++) {
            int kr = b_kr + i * 4;
            *(float4*)(&Bs[kr][b_c4]) =
                *(const float4*)(B + (size_t)(kt + kr) * ncols + b_c4);
        }
        __syncthreads();
#pragma unroll
        for (int k = 0; k < BK; k++) {
            float4 av = *(const float4*)(&As[k][ty * 4]);
            float4 bv = *(const float4*)(&Bs[k][tx * 4]);
            float ar[4] = {av.x, av.y, av.z, av.w};
            float br[4] = {bv.x, bv.y, bv.z, bv.w};
#pragma unroll
            for (int i = 0; i < 4; i++)
#pragma unroll
                for (int j = 0; j < 4; j++)
                    acc[i][j] = fmaf(ar[i], br[j], acc[i][j]);
        }
        __syncthreads();
    }

    const int r0 = row0 + ty * 4;
#pragma unroll
    for (int j = 0; j < 4; j++) {
        const int c = tx * 4 + j;
        const float bb = bias ? bias[c] : 0.0f;
        float4 o;
        o.x = __uint_as_float(tf32r(acc[0][j] + bb));
        o.y = __uint_as_float(tf32r(acc[1][j] + bb));
        o.z = __uint_as_float(tf32r(acc[2][j] + bb));
        o.w = __uint_as_float(tf32r(acc[3][j] + bb));
        *(float4*)(Yt + (size_t)c * M + r0) = o;
    }
}

__global__ __launch_bounds__(128) void sgemm_t_kernel(
    const float* __restrict__ A, const float* __restrict__ B,
    float* __restrict__ Yt, int M, int K, int ncols, const float* __restrict__ bias)
{
    sgemm_t_core(A, B, Yt, M, K, ncols, bias);
}

// batched-by-2: grid (M/BM, 2)
__global__ __launch_bounds__(128) void sgemm_t2_kernel(
    const float* __restrict__ A0, const float* __restrict__ A1,
    const float* __restrict__ B0, const float* __restrict__ B1,
    float* __restrict__ Y0, float* __restrict__ Y1,
    const float* __restrict__ c0, const float* __restrict__ c1,
    int M, int K, int ncols)
{
    if (blockIdx.y == 0) sgemm_t_core(A0, B0, Y0, M, K, ncols, c0);
    else                 sgemm_t_core(A1, B1, Y1, M, K, ncols, c1);
}

// =======================================================================
// post3: fused epilogue-GEMMs on P1 = sum(partP1), P3 = sum(partP3), 8 partials:
//  y=0: h2 = relu(P1 @ W2 + r1*b2 + h1)
//  y=1: z1 =      P1 @ W1h + r1*b1h
//  y=2: z3 =      P3 @ W3h + r3*b3h
// =======================================================================
__global__ __launch_bounds__(128) void post3_kernel(
    const float* __restrict__ partP1, const float* __restrict__ partP3,
    const float* __restrict__ rs1, const float* __restrict__ rs3,
    const float* __restrict__ W2,  const float* __restrict__ b2,
    const float* __restrict__ W1h, const float* __restrict__ b1h,
    const float* __restrict__ W3h, const float* __restrict__ b3h,
    const float* __restrict__ h1,
    float* __restrict__ h2, float* __restrict__ z1, float* __restrict__ z3)
{
    __shared__ float As[BK][BM];
    __shared__ float Bs[BK][128];

    const int yb = blockIdx.y;
    const float* P  = (yb == 2) ? partP3 : partP1;
    const float* rs = (yb == 2) ? rs3 : rs1;
    const float* W  = (yb == 0) ? W2 : (yb == 1) ? W1h : W3h;
    const float* bb = (yb == 0) ? b2 : (yb == 1) ? b1h : b3h;
    float* O        = (yb == 0) ? h2 : (yb == 1) ? z1 : z3;

    const int tid = threadIdx.x;
    const int tx = tid & 31;
    const int ty = tid >> 5;
    const int row0 = blockIdx.x * BM;

    float acc[4][4];
#pragma unroll
    for (int i = 0; i < 4; i++)
#pragma unroll
        for (int j = 0; j < 4; j++) acc[i][j] = 0.0f;

    const int a_row = tid >> 3;
    const int a_k4  = (tid & 7) * 4;
    const int b_c4  = (tid & 31) * 4;
    const int b_kr  = tid >> 5;

    for (int kt = 0; kt < HH; kt += BK) {
        float4 a = make_float4(0.f, 0.f, 0.f, 0.f);
#pragma unroll
        for (int z = 0; z < 8; z++) {
            float4 p = *(const float4*)(P + (size_t)z * SZ +
                                        (size_t)(row0 + a_row) * HH + kt + a_k4);
            a.x += p.x; a.y += p.y; a.z += p.z; a.w += p.w;
        }
        As[a_k4 + 0][a_row] = a.x;
        As[a_k4 + 1][a_row] = a.y;
        As[a_k4 + 2][a_row] = a.z;
        As[a_k4 + 3][a_row] = a.w;
#pragma unroll
        for (int i = 0; i < 8; i++) {
            int kr = b_kr + i * 4;
            *(float4*)(&Bs[kr][b_c4]) =
                *(const float4*)(W + (size_t)(kt + kr) * HH + b_c4);
        }
        __syncthreads();
#pragma unroll
        for (int k = 0; k < BK; k++) {
            float4 av = *(const float4*)(&As[k][ty * 4]);
            float4 bv = *(const float4*)(&Bs[k][tx * 4]);
            float ar[4] = {av.x, av.y, av.z, av.w};
            float br[4] = {bv.x, bv.y, bv.z, bv.w};
#pragma unroll
            for (int i = 0; i < 4; i++)
#pragma unroll
                for (int j = 0; j < 4; j++)
                    acc[i][j] = fmaf(ar[i], br[j], acc[i][j]);
        }
        __syncthreads();
    }

#pragma unroll
    for (int i = 0; i < 4; i++) {
        const int r = row0 + ty * 4 + i;
        float rv = 0.f;
        for (int z = 0; z < 8; z++) rv += rs[(size_t)z * NN + r];
        float4 o;
        float* op = (float*)&o;
#pragma unroll
        for (int j = 0; j < 4; j++) {
            const int c = tx * 4 + j;
            float v = acc[i][j] + rv * bb[c];
            if (yb == 0) {
                v += h1[(size_t)r * HH + c];
                v = fmaxf(v, 0.0f);
            }
            op[j] = v;
        }
        *(float4*)(O + (size_t)r * HH + tx * 4) = o;
    }
}

// ---------------- mixup combine (fp32 stacked output) ---------------------------
__global__ void mixcombine_kernel(const float* __restrict__ z1,
                                  const float* __restrict__ z3,
                                  const int* __restrict__ perm,
                                  const float* __restrict__ lam,
                                  float* __restrict__ stack)
{
    int i = blockIdx.x * blockDim.x + threadIdx.x;
    if (i >= SZ) return;
    int b = i >> 7;
    int t = i & 127;
    float l = lam[0];
    int pb = perm[b];
    stack[i]      = l * z1[i] + (1.0f - l) * z1[pb * HH + t];
    stack[SZ + i] = l * z3[i] + (1.0f - l) * z3[pb * HH + t];
}

// ---------------- L=2 self-attention -------------------------------------------
__global__ void attn_kernel(const float* __restrict__ qkv, float* __restrict__ obar,
                            int nh)
{
    int idx = blockIdx.x * blockDim.x + threadIdx.x;
    if (idx >= NN * nh) return;
    int b = idx / nh;
    int h = idx - b * nh;
    int hd = HH / nh;

    const float* base0 = qkv + (size_t)b * 384;
    const float* base1 = qkv + (size_t)NN * 384 + (size_t)b * 384;
    const float* q0 = base0 + h * hd;
    const float* k0 = base0 + 128 + h * hd;
    const float* v0 = base0 + 256 + h * hd;
    const float* q1 = base1 + h * hd;
    const float* k1 = base1 + 128 + h * hd;
    const float* v1 = base1 + 256 + h * hd;

    float s00 = 0.f, s01 = 0.f, s10 = 0.f, s11 = 0.f;
    for (int t = 0; t < hd; t++) {
        float a = q0[t], bq = q1[t], c = k0[t], d = k1[t];
        s00 = fmaf(a, c, s00);
        s01 = fmaf(a, d, s01);
        s10 = fmaf(bq, c, s10);
        s11 = fmaf(bq, d, s11);
    }
    float inv = rsqrtf((float)hd);
    s00 *= inv; s01 *= inv; s10 *= inv; s11 *= inv;

    float m0 = fmaxf(s00, s01);
    float e00 = expf(s00 - m0), e01 = expf(s01 - m0);
    float d0 = e00 + e01;
    float m1 = fmaxf(s10, s11);
    float e10 = expf(s10 - m1), e11 = expf(s11 - m1);
    float d1 = e10 + e11;

    float w0 = 0.5f * (e00 / d0 + e10 / d1);
    float w1 = 0.5f * (e01 / d0 + e11 / d1);

    float* ob = obar + (size_t)b * HH + h * hd;
    for (int t = 0; t < hd; t++)
        ob[t] = w0 * v0[t] + w1 * v1[t];
}

// ---------------- edge head ----------------------------------------------------
__global__ __launch_bounds__(256) void edge_kernel(
    const float* __restrict__ h3, const int* __restrict__ ei,
    const float* __restrict__ Wc, const float* __restrict__ bc,
    float* __restrict__ out)
{
    __shared__ float sWc[512];
    __shared__ float sbc[2];
    for (int i = threadIdx.x; i < 512; i += blockDim.x) sWc[i] = Wc[i];
    if (threadIdx.x < 2) sbc[threadIdx.x] = bc[threadIdx.x];
    __syncthreads();

    int warp = (blockIdx.x * blockDim.x + threadIdx.x) >> 5;
    int lane = threadIdx.x & 31;
    if (warp >= EE) return;

    int src = ei[warp];
    int dst = ei[EE + warp];
    float4 hs = *(const float4*)(h3 + (size_t)src * HH + lane * 4);
    float4 hd4 = *(const float4*)(h3 + (size_t)dst * HH + lane * 4);
    const float* hsp = (const float*)&hs;
    const float* hdp = (const float*)&hd4;

    float a0 = 0.f, a1 = 0.f;
#pragma unroll
    for (int i = 0; i < 4; i++) {
        int rsdx = lane * 4 + i;
        a0 = fmaf(hsp[i], sWc[rsdx * 2 + 0], a0);
        a0 = fmaf(hdp[i], sWc[(128 + rsdx) * 2 + 0], a0);
        a1 = fmaf(hsp[i], sWc[rsdx * 2 + 1], a1);
        a1 = fmaf(hdp[i], sWc[(128 + rsdx) * 2 + 1], a1);
    }
#pragma unroll
    for (int off = 16; off; off >>= 1) {
        a0 += __shfl_xor_sync(0xffffffffu, a0, off);
        a1 += __shfl_xor_sync(0xffffffffu, a1, off);
    }
    if (lane == 0) {
        out[(size_t)warp * 2 + 0] = a0 + sbc[0];
        out[(size_t)warp * 2 + 1] = a1 + sbc[1];
    }
}

// ---------------- host orchestration -------------------------------------------
extern "C" void kernel_launch(void* const* d_in, const int* in_sizes, int n_in,
                              void* d_out, int out_size)
{
    const float* x     = (const float*)d_in[0];
    const float* G1    = (const float*)d_in[1];
    const float* G3    = (const float*)d_in[2];
    const int*   ei    = (const int*)d_in[3];
    const int*   perm  = (const int*)d_in[4];
    const float* lam   = (const float*)d_in[5];
    const float* beta  = (const float*)d_in[6];
    const float* W1    = (const float*)d_in[7];  const float* b1   = (const float*)d_in[8];
    const float* W2    = (const float*)d_in[9];  const float* b2   = (const float*)d_in[10];
    const float* W3    = (const float*)d_in[11]; const float* b3   = (const float*)d_in[12];
    const float* W1h   = (const float*)d_in[13]; const float* b1h  = (const float*)d_in[14];
    const float* W3h   = (const float*)d_in[15]; const float* b3h  = (const float*)d_in[16];
    const float* W2m   = (const float*)d_in[17]; const float* b2m  = (const float*)d_in[18];
    const float* W3m   = (const float*)d_in[19]; const float* b3m  = (const float*)d_in[20];
    const float* WqkvM = (const float*)d_in[21]; const float* bqkvM= (const float*)d_in[22];
    const float* WoM   = (const float*)d_in[23]; const float* boM  = (const float*)d_in[24];
    const float* WqkvF = (const float*)d_in[25]; const float* bqkvF= (const float*)d_in[26];
    const float* WoF   = (const float*)d_in[27]; const float* boF  = (const float*)d_in[28];
    const float* Wc    = (const float*)d_in[29]; const float* bc   = (const float*)d_in[30];

    float *h1, *h2, *z1, *z3, *qkv, *obar, *h1mix, *part, *Yt, *h1t, *mix, *fus, *rs1, *rs3;
    cudaGetSymbolAddress((void**)&h1,    g_h1);
    cudaGetSymbolAddress((void**)&h2,    g_h2);
    cudaGetSymbolAddress((void**)&z1,    g_z1);
    cudaGetSymbolAddress((void**)&z3,    g_z3);
    cudaGetSymbolAddress((void**)&qkv,   g_qkv);
    cudaGetSymbolAddress((void**)&obar,  g_obar);
    cudaGetSymbolAddress((void**)&h1mix, g_h1mix);
    cudaGetSymbolAddress((void**)&part,  g_part);
    cudaGetSymbolAddress((void**)&Yt,    g_Yt);
    cudaGetSymbolAddress((void**)&h1t,   g_h1t);
    cudaGetSymbolAddress((void**)&mix,   g_mix);
    cudaGetSymbolAddress((void**)&fus,   g_fus);
    cudaGetSymbolAddress((void**)&rs1,   g_rs1);
    cudaGetSymbolAddress((void**)&rs3,   g_rs3);

    float* out = (float*)d_out;
    float* h3  = out + (size_t)EE * 2;

    const size_t sz = (size_t)SZ;
    float* Yt0 = Yt;
    float* Yt1 = Yt + (size_t)HH * NN;

    const int red_grid = (SZ / 4 + 255) / 256;
    const dim3 rt_grid(NN / 32, HH / 32), rt_blk(32, 8);

    // ---- h1 = relu(G1 @ (x W1 + b1)), KS=8; also emits rowsum(G1) partials ----
    sgemm_t_kernel<<<NN / BM, 128>>>(x, W1, Yt0, NN, HH, HH, b1);
    tgemm_kernel<<<dim3(NN / 64, 1, 8), 256>>>(G1, Yt0, part, NN, NN, HH, nullptr, rs1);
    reduceN_t_kernel<<<rt_grid, rt_blk>>>(part, 8, h1, h1t);

    // ---- P1 = G1@h1, P3 = G3@h1 (batched, KS=8); emits rowsum(G3) partials ----
    tgemm2_kernel<<<dim3(NN / 64, 2, 8), 256>>>(G1, G3, h1t, h1t,
                                                part, part + 8 * sz,
                                                nullptr, rs3, NN, NN);
    // ---- h2, z1, z3 via reassociation: G@(hW+b) = (G@h)W + (G@1) b ----
    post3_kernel<<<dim3(NN / BM, 3), 128>>>(part, part + 8 * sz, rs1, rs3,
                                            W2, b2, W1h, b1h, W3h, b3h,
                                            h1, h2, z1, z3);

    // ---- mixup (permuted-graph term == z[perm]) ----
    mixcombine_kernel<<<(SZ + 255) / 256, 256>>>(z1, z3, perm, lam, mix);

    // ---- MHA mix (nh=2) ----
    tgemm_kernel<<<dim3(2 * NN / 64, 3, 1), 256>>>(mix, WqkvM, qkv, 2 * NN, HH, 3 * HH, bqkvM, nullptr);
    attn_kernel<<<(NN * 2 + 255) / 256, 256>>>(qkv, obar, 2);
    tgemm_kernel<<<dim3(NN / 64, 1, 1), 256>>>(obar, WoM, h1mix, NN, HH, HH, boM, nullptr);

    // ---- batched: h3_c1 big GEMM (G1@(h2 W3+b3)) + h2m big GEMM (G1@(h1mix W2m+b2m)) ----
    sgemm_t2_kernel<<<dim3(NN / BM, 2), 128>>>(h2, h1mix, W3, W2m, Yt0, Yt1,
                                               b3, b2m, NN, HH, HH);
    tgemm2_kernel<<<dim3(NN / 64, 2, 8), 256>>>(G1, G1, Yt0, Yt1,
                                                part, part + 8 * sz,
                                                nullptr, nullptr, NN, NN);
    reduceN_kernel<<<red_grid, 256>>>(part,          fus, h2, 1, nullptr, 8);      // h3_c1
    reduceN_kernel<<<red_grid, 256>>>(part + 8 * sz, h2, h1mix, 1, nullptr, 8);    // h2_mix (reuse h2)

    // ---- h3_c2 = relu(G1 @ (h2m W3m + b3m) + h2m) * beta -> fus[1], KS=8 ----
    sgemm_t_kernel<<<NN / BM, 128>>>(h2, W3m, Yt0, NN, HH, HH, b3m);
    tgemm_kernel<<<dim3(NN / 64, 1, 8), 256>>>(G1, Yt0, part, NN, NN, HH, nullptr, nullptr);
    reduceN_kernel<<<red_grid, 256>>>(part, fus + sz, h2, 1, beta, 8);

    // ---- MHA fus (nh=4) ----
    tgemm_kernel<<<dim3(2 * NN / 64, 3, 1), 256>>>(fus, WqkvF, qkv, 2 * NN, HH, 3 * HH, bqkvF, nullptr);
    attn_kernel<<<(NN * 4 + 255) / 256, 256>>>(qkv, obar, 4);
    tgemm_kernel<<<dim3(NN / 64, 1, 1), 256>>>(obar, WoF, h3, NN, HH, HH, boF, nullptr);

    // ---- edge predictions ----
    edge_kernel<<<EE / 8, 256>>>(h3, ei, Wc, bc, out);
}

// round 14
// speedup vs baseline: 1.1229x; 1.1229x over previous
#include <cuda_runtime.h>
#include <cuda_bf16.h>
#include <cstdint>
#include <math.h>

// Problem constants
#define NN 4096
#define HH 128
#define EE 131072
#define SZ (NN * HH)

// ---------------- scratch (static device arrays; no allocation) ----------------
__device__ float g_h1[SZ];
__device__ float g_h2[SZ];
__device__ float g_z1[SZ];
__device__ float g_z3[SZ];
__device__ float g_qkv[2 * NN * 3 * HH];
__device__ float g_obar[SZ];
__device__ float g_h1mix[SZ];
__device__ float g_part[16 * SZ];         // split-K partials
__device__ float g_Yt[2 * HH * NN];       // transposed tf32 Y buffers (contiguous!)
__device__ float g_h1t[HH * NN];          // h1^T tf32
__device__ float g_mix[2 * SZ];
__device__ float g_fus[2 * SZ];
__device__ float g_rs1[8 * NN];           // rowsum(G1) partials (KS=8)
__device__ float g_rs3[8 * NN];           // rowsum(G3) partials (KS=8)

// ---------------- helpers -------------------------------------------------------
__device__ __forceinline__ unsigned tf32r(float v) {
    unsigned u;
    asm("cvt.rna.tf32.f32 %0, %1;" : "=r"(u) : "f"(v));
    return u;
}

#define MMA_TF32(d, a0, a1, a2, a3, b0, b1)                                   \
    asm volatile(                                                             \
        "mma.sync.aligned.m16n8k8.row.col.f32.tf32.tf32.f32 "                 \
        "{%0,%1,%2,%3}, {%4,%5,%6,%7}, {%8,%9}, {%0,%1,%2,%3};"               \
        : "+f"(d[0]), "+f"(d[1]), "+f"(d[2]), "+f"(d[3])                      \
        : "r"(a0), "r"(a1), "r"(a2), "r"(a3), "r"(b0), "r"(b1))

// =======================================================================
// tf32 GEMM core (R11-proven, 128x128 CTA tile): C[M,Nc] = A[M,K] @ B[K,Nc],
// B transposed [Nc][K]. KS>1: partial at C + kz*M*Nc, no bias.
// Optional rowsum(A) partial rs[kz*M + row].
// =======================================================================
__device__ __forceinline__ void tgemm_core(
    const float* __restrict__ A, const float* __restrict__ Bt,
    float* __restrict__ C, int M, int K, int Nc, int col0,
    const float* __restrict__ bias, int KS, int kz, float* __restrict__ rs)
{
    __shared__ float sA[128][36];
    __shared__ float sB[128][36];

    const int tid  = threadIdx.x;
    const int row0 = blockIdx.x * 128;
    const int kiters = K / (32 * KS);
    const int kbase  = kz * kiters * 32;

    const int warp = tid >> 5, lane = tid & 31;
    const int wm = warp & 3, wn = warp >> 2;
    const int grp = lane >> 2, thr4 = lane & 3;

    float acc[2][8][4];
#pragma unroll
    for (int mf = 0; mf < 2; mf++)
#pragma unroll
        for (int nf = 0; nf < 8; nf++)
#pragma unroll
            for (int i = 0; i < 4; i++) acc[mf][nf][i] = 0.0f;

    const int l_r = tid >> 1;
    const int l_c = (tid & 1) * 16;
    const float* gA = A  + (size_t)(row0 + l_r) * K + kbase + l_c;
    const float* gB = Bt + (size_t)(col0 + l_r) * K + kbase + l_c;

    float4 pa[4], pb[4];
#pragma unroll
    for (int i = 0; i < 4; i++) {
        pa[i] = *(const float4*)(gA + i * 4);
        pb[i] = *(const float4*)(gB + i * 4);
    }

    float asum = 0.0f;

    for (int it = 0; it < kiters; it++) {
#pragma unroll
        for (int i = 0; i < 4; i++) {
            uint4 ta, tb;
            ta.x = tf32r(pa[i].x); ta.y = tf32r(pa[i].y);
            ta.z = tf32r(pa[i].z); ta.w = tf32r(pa[i].w);
            tb.x = tf32r(pb[i].x); tb.y = tf32r(pb[i].y);
            tb.z = tf32r(pb[i].z); tb.w = tf32r(pb[i].w);
            *(uint4*)&sA[l_r][l_c + i * 4] = ta;
            *(uint4*)&sB[l_r][l_c + i * 4] = tb;
        }
        if (rs) {
#pragma unroll
            for (int i = 0; i < 4; i++)
                asum += (pa[i].x + pa[i].y) + (pa[i].z + pa[i].w);
        }
        __syncthreads();

        if (it + 1 < kiters) {
            const int ko = (it + 1) * 32;
#pragma unroll
            for (int i = 0; i < 4; i++) {
                pa[i] = *(const float4*)(gA + ko + i * 4);
                pb[i] = *(const float4*)(gB + ko + i * 4);
            }
        }

#pragma unroll
        for (int koff = 0; koff < 32; koff += 8) {
            const int c0 = koff + thr4;
            unsigned a[2][4];
#pragma unroll
            for (int mf = 0; mf < 2; mf++) {
                const int mb = wm * 32 + mf * 16;
                a[mf][0] = *(const unsigned*)&sA[mb + grp][c0];
                a[mf][1] = *(const unsigned*)&sA[mb + grp + 8][c0];
                a[mf][2] = *(const unsigned*)&sA[mb + grp][c0 + 4];
                a[mf][3] = *(const unsigned*)&sA[mb + grp + 8][c0 + 4];
            }
#pragma unroll
            for (int nf = 0; nf < 8; nf++) {
                const int nb = wn * 64 + nf * 8;
                unsigned b0 = *(const unsigned*)&sB[nb + grp][c0];
                unsigned b1 = *(const unsigned*)&sB[nb + grp][c0 + 4];
#pragma unroll
                for (int mf = 0; mf < 2; mf++)
                    MMA_TF32(acc[mf][nf], a[mf][0], a[mf][1], a[mf][2], a[mf][3], b0, b1);
            }
        }
        __syncthreads();
    }

    if (rs) {
        float tot = asum + __shfl_xor_sync(0xffffffffu, asum, 1);
        if ((tid & 1) == 0)
            rs[(size_t)kz * M + row0 + l_r] = tot;
    }

    float* Co = (KS > 1) ? C + (size_t)kz * M * Nc : C;
#pragma unroll
    for (int mf = 0; mf < 2; mf++) {
        const int m = row0 + wm * 32 + mf * 16 + grp;
#pragma unroll
        for (int nf = 0; nf < 8; nf++) {
            const int n = col0 + wn * 64 + nf * 8 + thr4 * 2;
            float b0 = 0.f, b1 = 0.f;
            if (bias) { b0 = bias[n]; b1 = bias[n + 1]; }
            float2 v0 = make_float2(acc[mf][nf][0] + b0, acc[mf][nf][1] + b1);
            float2 v1 = make_float2(acc[mf][nf][2] + b0, acc[mf][nf][3] + b1);
            *(float2*)(Co + (size_t)m * Nc + n) = v0;
            *(float2*)(Co + (size_t)(m + 8) * Nc + n) = v1;
        }
    }
}

// standard entry: grid (M/128, Nc/128, KS)
__global__ __launch_bounds__(256) void tgemm_kernel(
    const float* __restrict__ A, const float* __restrict__ Bt,
    float* __restrict__ C, int M, int K, int Nc, const float* __restrict__ bias,
    float* __restrict__ rs)
{
    tgemm_core(A, Bt, C, M, K, Nc, blockIdx.y * 128, bias,
               gridDim.z, blockIdx.z, blockIdx.y == 0 ? rs : nullptr);
}

// batched-by-2 entry (Nc=128): grid (M/128, 2, KS)
__global__ __launch_bounds__(256) void tgemm2_kernel(
    const float* __restrict__ A0, const float* __restrict__ A1,
    const float* __restrict__ B0, const float* __restrict__ B1,
    float* __restrict__ C0, float* __restrict__ C1,
    float* __restrict__ rsa, float* __restrict__ rsb,
    int M, int K)
{
    const float* A = blockIdx.y ? A1 : A0;
    const float* B = blockIdx.y ? B1 : B0;
    float*       C = blockIdx.y ? C1 : C0;
    float*       r = blockIdx.y ? rsb : rsa;
    tgemm_core(A, B, C, M, K, 128, 0, nullptr, gridDim.z, blockIdx.z, r);
}

// ---------------- split-K reduce + epilogue (KS partials) ----------------------
__global__ void reduceN_kernel(const float* __restrict__ part, float* __restrict__ C,
                               const float* __restrict__ resid, int do_relu,
                               const float* __restrict__ scale_ptr, int KS)
{
    int i = (blockIdx.x * blockDim.x + threadIdx.x) * 4;
    if (i >= SZ) return;
    float v[4] = {0.f, 0.f, 0.f, 0.f};
    for (int z = 0; z < KS; z++) {
        float4 p = *(const float4*)(part + (size_t)z * SZ + i);
        v[0] += p.x; v[1] += p.y; v[2] += p.z; v[3] += p.w;
    }
    if (resid) {
        float4 r = *(const float4*)(resid + i);
        v[0] += r.x; v[1] += r.y; v[2] += r.z; v[3] += r.w;
    }
    float s = scale_ptr ? *scale_ptr : 1.0f;
#pragma unroll
    for (int j = 0; j < 4; j++) {
        if (do_relu) v[j] = fmaxf(v[j], 0.0f);
        v[j] *= s;
    }
    *(float4*)(C + i) = make_float4(v[0], v[1], v[2], v[3]);
}

// ---- fused reduce for the Nc=256 pair GEMM: partials are [kz][NN][256]. --------
// cols 0-127  -> fus[0] = relu(sum + h2_old)
// cols 128-255-> h2     = relu(sum + h1mix)
// Each thread handles the SAME (r, c) for both halves: reads old h2 before write.
__global__ void reduceN2_kernel(const float* __restrict__ part,
                                const float* __restrict__ h1mix,
                                float* __restrict__ fus0, float* __restrict__ h2)
{
    int i = (blockIdx.x * blockDim.x + threadIdx.x) * 4;
    if (i >= SZ) return;
    int r = i >> 7;
    int c = i & 127;
    size_t base = (size_t)r * 256 + c;
    float a[4] = {0.f, 0.f, 0.f, 0.f};
    float b[4] = {0.f, 0.f, 0.f, 0.f};
    for (int z = 0; z < 8; z++) {
        float4 p = *(const float4*)(part + (size_t)z * 2 * SZ + base);
        float4 q = *(const float4*)(part + (size_t)z * 2 * SZ + base + 128);
        a[0] += p.x; a[1] += p.y; a[2] += p.z; a[3] += p.w;
        b[0] += q.x; b[1] += q.y; b[2] += q.z; b[3] += q.w;
    }
    float4 h2o = *(const float4*)(h2 + i);
    float4 h1m = *(const float4*)(h1mix + i);
    float4 of, oh;
    of.x = fmaxf(a[0] + h2o.x, 0.f);
    of.y = fmaxf(a[1] + h2o.y, 0.f);
    of.z = fmaxf(a[2] + h2o.z, 0.f);
    of.w = fmaxf(a[3] + h2o.w, 0.f);
    oh.x = fmaxf(b[0] + h1m.x, 0.f);
    oh.y = fmaxf(b[1] + h1m.y, 0.f);
    oh.z = fmaxf(b[2] + h1m.z, 0.f);
    oh.w = fmaxf(b[3] + h1m.w, 0.f);
    *(float4*)(fus0 + i) = of;
    *(float4*)(h2 + i) = oh;
}

// ---- reduce + relu + ALSO write tf32 transposed copy (for h1) ------------------
// grid (NN/32, HH/32), block (32, 8)
__global__ void reduceN_t_kernel(const float* __restrict__ part, int KS,
                                 float* __restrict__ O, float* __restrict__ Ot)
{
    __shared__ float t[32][33];
    const int r0 = blockIdx.x * 32, c0 = blockIdx.y * 32;
    const int tx = threadIdx.x, ty = threadIdx.y;
#pragma unroll
    for (int q = 0; q < 4; q++) {
        int r = r0 + ty + q * 8;
        int c = c0 + tx;
        float v = 0.f;
        for (int z = 0; z < KS; z++)
            v += part[(size_t)z * SZ + (size_t)r * HH + c];
        v = fmaxf(v, 0.0f);
        O[(size_t)r * HH + c] = v;
        t[ty + q * 8][tx] = v;
    }
    __syncthreads();
#pragma unroll
    for (int q = 0; q < 4; q++) {
        int c = c0 + ty + q * 8;
        int r = r0 + tx;
        Ot[(size_t)c * NN + r] = __uint_as_float(tf32r(t[tx][ty + q * 8]));
    }
}

// =======================================================================
// FFMA small GEMM (K=128, ncols=128): Yt[c][r] = tf32(A@B + b)
// =======================================================================
#define BM 16
#define BK 32

__device__ __forceinline__ void sgemm_t_core(
    const float* __restrict__ A, const float* __restrict__ B,
    float* __restrict__ Yt, int M, int K, int ncols,
    const float* __restrict__ bias)
{
    __shared__ float As[BK][BM];
    __shared__ float Bs[BK][128];

    const int tid = threadIdx.x;
    const int tx = tid & 31;
    const int ty = tid >> 5;
    const int row0 = blockIdx.x * BM;

    float acc[4][4];
#pragma unroll
    for (int i = 0; i < 4; i++)
#pragma unroll
        for (int j = 0; j < 4; j++) acc[i][j] = 0.0f;

    const int a_row = tid >> 3;
    const int a_k4  = (tid & 7) * 4;
    const int b_c4  = (tid & 31) * 4;
    const int b_kr  = tid >> 5;

    for (int kt = 0; kt < K; kt += BK) {
        float4 a = *(const float4*)(A + (size_t)(row0 + a_row) * K + kt + a_k4);
        As[a_k4 + 0][a_row] = a.x;
        As[a_k4 + 1][a_row] = a.y;
        As[a_k4 + 2][a_row] = a.z;
        As[a_k4 + 3][a_row] = a.w;
#pragma unroll
        for (int i = 0; i < 8; i++) {
            int kr = b_kr + i * 4;
            *(float4*)(&Bs[kr][b_c4]) =
                *(const float4*)(B + (size_t)(kt + kr) * ncols + b_c4);
        }
        __syncthreads();
#pragma unroll
        for (int k = 0; k < BK; k++) {
            float4 av = *(const float4*)(&As[k][ty * 4]);
            float4 bv = *(const float4*)(&Bs[k][tx * 4]);
            float ar[4] = {av.x, av.y, av.z, av.w};
            float br[4] = {bv.x, bv.y, bv.z, bv.w};
#pragma unroll
            for (int i = 0; i < 4; i++)
#pragma unroll
                for (int j = 0; j < 4; j++)
                    acc[i][j] = fmaf(ar[i], br[j], acc[i][j]);
        }
        __syncthreads();
    }

    const int r0 = row0 + ty * 4;
#pragma unroll
    for (int j = 0; j < 4; j++) {
        const int c = tx * 4 + j;
        const float bb = bias ? bias[c] : 0.0f;
        float4 o;
        o.x = __uint_as_float(tf32r(acc[0][j] + bb));
        o.y = __uint_as_float(tf32r(acc[1][j] + bb));
        o.z = __uint_as_float(tf32r(acc[2][j] + bb));
        o.w = __uint_as_float(tf32r(acc[3][j] + bb));
        *(float4*)(Yt + (size_t)c * M + r0) = o;
    }
}

__global__ __launch_bounds__(128) void sgemm_t_kernel(
    const float* __restrict__ A, const float* __restrict__ B,
    float* __restrict__ Yt, int M, int K, int ncols, const float* __restrict__ bias)
{
    sgemm_t_core(A, B, Yt, M, K, ncols, bias);
}

// batched-by-2: grid (M/BM, 2)
__global__ __launch_bounds__(128) void sgemm_t2_kernel(
    const float* __restrict__ A0, const float* __restrict__ A1,
    const float* __restrict__ B0, const float* __restrict__ B1,
    float* __restrict__ Y0, float* __restrict__ Y1,
    const float* __restrict__ c0, const float* __restrict__ c1,
    int M, int K, int ncols)
{
    if (blockIdx.y == 0) sgemm_t_core(A0, B0, Y0, M, K, ncols, c0);
    else                 sgemm_t_core(A1, B1, Y1, M, K, ncols, c1);
}

// =======================================================================
// post3: fused epilogue-GEMMs on P1 = sum(partP1), P3 = sum(partP3), 8 partials:
//  y=0: h2 = relu(P1 @ W2 + r1*b2 + h1)
//  y=1: z1 =      P1 @ W1h + r1*b1h
//  y=2: z3 =      P3 @ W3h + r3*b3h
// =======================================================================
__global__ __launch_bounds__(128) void post3_kernel(
    const float* __restrict__ partP1, const float* __restrict__ partP3,
    const float* __restrict__ rs1, const float* __restrict__ rs3,
    const float* __restrict__ W2,  const float* __restrict__ b2,
    const float* __restrict__ W1h, const float* __restrict__ b1h,
    const float* __restrict__ W3h, const float* __restrict__ b3h,
    const float* __restrict__ h1,
    float* __restrict__ h2, float* __restrict__ z1, float* __restrict__ z3)
{
    __shared__ float As[BK][BM];
    __shared__ float Bs[BK][128];

    const int yb = blockIdx.y;
    const float* P  = (yb == 2) ? partP3 : partP1;
    const float* rs = (yb == 2) ? rs3 : rs1;
    const float* W  = (yb == 0) ? W2 : (yb == 1) ? W1h : W3h;
    const float* bb = (yb == 0) ? b2 : (yb == 1) ? b1h : b3h;
    float* O        = (yb == 0) ? h2 : (yb == 1) ? z1 : z3;

    const int tid = threadIdx.x;
    const int tx = tid & 31;
    const int ty = tid >> 5;
    const int row0 = blockIdx.x * BM;

    float acc[4][4];
#pragma unroll
    for (int i = 0; i < 4; i++)
#pragma unroll
        for (int j = 0; j < 4; j++) acc[i][j] = 0.0f;

    const int a_row = tid >> 3;
    const int a_k4  = (tid & 7) * 4;
    const int b_c4  = (tid & 31) * 4;
    const int b_kr  = tid >> 5;

    for (int kt = 0; kt < HH; kt += BK) {
        float4 a = make_float4(0.f, 0.f, 0.f, 0.f);
#pragma unroll
        for (int z = 0; z < 8; z++) {
            float4 p = *(const float4*)(P + (size_t)z * SZ +
                                        (size_t)(row0 + a_row) * HH + kt + a_k4);
            a.x += p.x; a.y += p.y; a.z += p.z; a.w += p.w;
        }
        As[a_k4 + 0][a_row] = a.x;
        As[a_k4 + 1][a_row] = a.y;
        As[a_k4 + 2][a_row] = a.z;
        As[a_k4 + 3][a_row] = a.w;
#pragma unroll
        for (int i = 0; i < 8; i++) {
            int kr = b_kr + i * 4;
            *(float4*)(&Bs[kr][b_c4]) =
                *(const float4*)(W + (size_t)(kt + kr) * HH + b_c4);
        }
        __syncthreads();
#pragma unroll
        for (int k = 0; k < BK; k++) {
            float4 av = *(const float4*)(&As[k][ty * 4]);
            float4 bv = *(const float4*)(&Bs[k][tx * 4]);
            float ar[4] = {av.x, av.y, av.z, av.w};
            float br[4] = {bv.x, bv.y, bv.z, bv.w};
#pragma unroll
            for (int i = 0; i < 4; i++)
#pragma unroll
                for (int j = 0; j < 4; j++)
                    acc[i][j] = fmaf(ar[i], br[j], acc[i][j]);
        }
        __syncthreads();
    }

#pragma unroll
    for (int i = 0; i < 4; i++) {
        const int r = row0 + ty * 4 + i;
        float rv = 0.f;
        for (int z = 0; z < 8; z++) rv += rs[(size_t)z * NN + r];
        float4 o;
        float* op = (float*)&o;
#pragma unroll
        for (int j = 0; j < 4; j++) {
            const int c = tx * 4 + j;
            float v = acc[i][j] + rv * bb[c];
            if (yb == 0) {
                v += h1[(size_t)r * HH + c];
                v = fmaxf(v, 0.0f);
            }
            op[j] = v;
        }
        *(float4*)(O + (size_t)r * HH + tx * 4) = o;
    }
}

// ---------------- mixup combine (fp32 stacked output) ---------------------------
__global__ void mixcombine_kernel(const float* __restrict__ z1,
                                  const float* __restrict__ z3,
                                  const int* __restrict__ perm,
                                  const float* __restrict__ lam,
                                  float* __restrict__ stack)
{
    int i = blockIdx.x * blockDim.x + threadIdx.x;
    if (i >= SZ) return;
    int b = i >> 7;
    int t = i & 127;
    float l = lam[0];
    int pb = perm[b];
    stack[i]      = l * z1[i] + (1.0f - l) * z1[pb * HH + t];
    stack[SZ + i] = l * z3[i] + (1.0f - l) * z3[pb * HH + t];
}

// ---------------- L=2 self-attention -------------------------------------------
__global__ void attn_kernel(const float* __restrict__ qkv, float* __restrict__ obar,
                            int nh)
{
    int idx = blockIdx.x * blockDim.x + threadIdx.x;
    if (idx >= NN * nh) return;
    int b = idx / nh;
    int h = idx - b * nh;
    int hd = HH / nh;

    const float* base0 = qkv + (size_t)b * 384;
    const float* base1 = qkv + (size_t)NN * 384 + (size_t)b * 384;
    const float* q0 = base0 + h * hd;
    const float* k0 = base0 + 128 + h * hd;
    const float* v0 = base0 + 256 + h * hd;
    const float* q1 = base1 + h * hd;
    const float* k1 = base1 + 128 + h * hd;
    const float* v1 = base1 + 256 + h * hd;

    float s00 = 0.f, s01 = 0.f, s10 = 0.f, s11 = 0.f;
    for (int t = 0; t < hd; t++) {
        float a = q0[t], bq = q1[t], c = k0[t], d = k1[t];
        s00 = fmaf(a, c, s00);
        s01 = fmaf(a, d, s01);
        s10 = fmaf(bq, c, s10);
        s11 = fmaf(bq, d, s11);
    }
    float inv = rsqrtf((float)hd);
    s00 *= inv; s01 *= inv; s10 *= inv; s11 *= inv;

    float m0 = fmaxf(s00, s01);
    float e00 = expf(s00 - m0), e01 = expf(s01 - m0);
    float d0 = e00 + e01;
    float m1 = fmaxf(s10, s11);
    float e10 = expf(s10 - m1), e11 = expf(s11 - m1);
    float d1 = e10 + e11;

    float w0 = 0.5f * (e00 / d0 + e10 / d1);
    float w1 = 0.5f * (e01 / d0 + e11 / d1);

    float* ob = obar + (size_t)b * HH + h * hd;
    for (int t = 0; t < hd; t++)
        ob[t] = w0 * v0[t] + w1 * v1[t];
}

// ---------------- edge head ----------------------------------------------------
__global__ __launch_bounds__(256) void edge_kernel(
    const float* __restrict__ h3, const int* __restrict__ ei,
    const float* __restrict__ Wc, const float* __restrict__ bc,
    float* __restrict__ out)
{
    __shared__ float sWc[512];
    __shared__ float sbc[2];
    for (int i = threadIdx.x; i < 512; i += blockDim.x) sWc[i] = Wc[i];
    if (threadIdx.x < 2) sbc[threadIdx.x] = bc[threadIdx.x];
    __syncthreads();

    int warp = (blockIdx.x * blockDim.x + threadIdx.x) >> 5;
    int lane = threadIdx.x & 31;
    if (warp >= EE) return;

    int src = ei[warp];
    int dst = ei[EE + warp];
    float4 hs = *(const float4*)(h3 + (size_t)src * HH + lane * 4);
    float4 hd4 = *(const float4*)(h3 + (size_t)dst * HH + lane * 4);
    const float* hsp = (const float*)&hs;
    const float* hdp = (const float*)&hd4;

    float a0 = 0.f, a1 = 0.f;
#pragma unroll
    for (int i = 0; i < 4; i++) {
        int rsdx = lane * 4 + i;
        a0 = fmaf(hsp[i], sWc[rsdx * 2 + 0], a0);
        a0 = fmaf(hdp[i], sWc[(128 + rsdx) * 2 + 0], a0);
        a1 = fmaf(hsp[i], sWc[rsdx * 2 + 1], a1);
        a1 = fmaf(hdp[i], sWc[(128 + rsdx) * 2 + 1], a1);
    }
#pragma unroll
    for (int off = 16; off; off >>= 1) {
        a0 += __shfl_xor_sync(0xffffffffu, a0, off);
        a1 += __shfl_xor_sync(0xffffffffu, a1, off);
    }
    if (lane == 0) {
        out[(size_t)warp * 2 + 0] = a0 + sbc[0];
        out[(size_t)warp * 2 + 1] = a1 + sbc[1];
    }
}

// ---------------- host orchestration -------------------------------------------
extern "C" void kernel_launch(void* const* d_in, const int* in_sizes, int n_in,
                              void* d_out, int out_size)
{
    const float* x     = (const float*)d_in[0];
    const float* G1    = (const float*)d_in[1];
    const float* G3    = (const float*)d_in[2];
    const int*   ei    = (const int*)d_in[3];
    const int*   perm  = (const int*)d_in[4];
    const float* lam   = (const float*)d_in[5];
    const float* beta  = (const float*)d_in[6];
    const float* W1    = (const float*)d_in[7];  const float* b1   = (const float*)d_in[8];
    const float* W2    = (const float*)d_in[9];  const float* b2   = (const float*)d_in[10];
    const float* W3    = (const float*)d_in[11]; const float* b3   = (const float*)d_in[12];
    const float* W1h   = (const float*)d_in[13]; const float* b1h  = (const float*)d_in[14];
    const float* W3h   = (const float*)d_in[15]; const float* b3h  = (const float*)d_in[16];
    const float* W2m   = (const float*)d_in[17]; const float* b2m  = (const float*)d_in[18];
    const float* W3m   = (const float*)d_in[19]; const float* b3m  = (const float*)d_in[20];
    const float* WqkvM = (const float*)d_in[21]; const float* bqkvM= (const float*)d_in[22];
    const float* WoM   = (const float*)d_in[23]; const float* boM  = (const float*)d_in[24];
    const float* WqkvF = (const float*)d_in[25]; const float* bqkvF= (const float*)d_in[26];
    const float* WoF   = (const float*)d_in[27]; const float* boF  = (const float*)d_in[28];
    const float* Wc    = (const float*)d_in[29]; const float* bc   = (const float*)d_in[30];

    float *h1, *h2, *z1, *z3, *qkv, *obar, *h1mix, *part, *Yt, *h1t, *mix, *fus, *rs1, *rs3;
    cudaGetSymbolAddress((void**)&h1,    g_h1);
    cudaGetSymbolAddress((void**)&h2,    g_h2);
    cudaGetSymbolAddress((void**)&z1,    g_z1);
    cudaGetSymbolAddress((void**)&z3,    g_z3);
    cudaGetSymbolAddress((void**)&qkv,   g_qkv);
    cudaGetSymbolAddress((void**)&obar,  g_obar);
    cudaGetSymbolAddress((void**)&h1mix, g_h1mix);
    cudaGetSymbolAddress((void**)&part,  g_part);
    cudaGetSymbolAddress((void**)&Yt,    g_Yt);
    cudaGetSymbolAddress((void**)&h1t,   g_h1t);
    cudaGetSymbolAddress((void**)&mix,   g_mix);
    cudaGetSymbolAddress((void**)&fus,   g_fus);
    cudaGetSymbolAddress((void**)&rs1,   g_rs1);
    cudaGetSymbolAddress((void**)&rs3,   g_rs3);

    float* out = (float*)d_out;
    float* h3  = out + (size_t)EE * 2;

    const size_t sz = (size_t)SZ;
    float* Yt0 = Yt;
    float* Yt1 = Yt + (size_t)HH * NN;

    const int red_grid = (SZ / 4 + 255) / 256;
    const dim3 rt_grid(NN / 32, HH / 32), rt_blk(32, 8);

    // ---- h1 = relu(G1 @ (x W1 + b1)), KS=8; also emits rowsum(G1) partials ----
    sgemm_t_kernel<<<NN / BM, 128>>>(x, W1, Yt0, NN, HH, HH, b1);
    tgemm_kernel<<<dim3(NN / 128, 1, 8), 256>>>(G1, Yt0, part, NN, NN, HH, nullptr, rs1);
    reduceN_t_kernel<<<rt_grid, rt_blk>>>(part, 8, h1, h1t);

    // ---- P1 = G1@h1, P3 = G3@h1 (batched, KS=8); emits rowsum(G3) partials ----
    tgemm2_kernel<<<dim3(NN / 128, 2, 8), 256>>>(G1, G3, h1t, h1t,
                                                 part, part + 8 * sz,
                                                 nullptr, rs3, NN, NN);
    // ---- h2, z1, z3 via reassociation: G@(hW+b) = (G@h)W + (G@1) b ----
    post3_kernel<<<dim3(NN / BM, 3), 128>>>(part, part + 8 * sz, rs1, rs3,
                                            W2, b2, W1h, b1h, W3h, b3h,
                                            h1, h2, z1, z3);

    // ---- mixup (permuted-graph term == z[perm]) ----
    mixcombine_kernel<<<(SZ + 255) / 256, 256>>>(z1, z3, perm, lam, mix);

    // ---- MHA mix (nh=2) ----
    tgemm_kernel<<<dim3(2 * NN / 128, 3, 1), 256>>>(mix, WqkvM, qkv, 2 * NN, HH, 3 * HH, bqkvM, nullptr);
    attn_kernel<<<(NN * 2 + 255) / 256, 256>>>(qkv, obar, 2);
    tgemm_kernel<<<dim3(NN / 128, 1, 1), 256>>>(obar, WoM, h1mix, NN, HH, HH, boM, nullptr);

    // ---- fused pair as ONE Nc=256 GEMM: G1 @ [Yt0 (h2 W3+b3) ; Yt1 (h1mix W2m+b2m)] ----
    sgemm_t2_kernel<<<dim3(NN / BM, 2), 128>>>(h2, h1mix, W3, W2m, Yt0, Yt1,
                                               b3, b2m, NN, HH, HH);
    tgemm_kernel<<<dim3(NN / 128, 2, 8), 256>>>(G1, Yt, part, NN, NN, 256, nullptr, nullptr);
    reduceN2_kernel<<<red_grid, 256>>>(part, h1mix, fus, h2);   // fus[0]=h3_c1, h2=h2_mix

    // ---- h3_c2 = relu(G1 @ (h2m W3m + b3m) + h2m) * beta -> fus[1], KS=8 ----
    sgemm_t_kernel<<<NN / BM, 128>>>(h2, W3m, Yt0, NN, HH, HH, b3m);
    tgemm_kernel<<<dim3(NN / 128, 1, 8), 256>>>(G1, Yt0, part, NN, NN, HH, nullptr, nullptr);
    reduceN_kernel<<<red_grid, 256>>>(part, fus + sz, h2, 1, beta, 8);

    // ---- MHA fus (nh=4) ----
    tgemm_kernel<<<dim3(2 * NN / 128, 3, 1), 256>>>(fus, WqkvF, qkv, 2 * NN, HH, 3 * HH, bqkvF, nullptr);
    attn_kernel<<<(NN * 4 + 255) / 256, 256>>>(qkv, obar, 4);
    tgemm_kernel<<<dim3(NN / 128, 1, 1), 256>>>(obar, WoF, h3, NN, HH, HH, boF, nullptr);

    // ---- edge predictions ----
    edge_kernel<<<EE / 8, 256>>>(h3, ei, Wc, bc, out);
}